// round 2
// baseline (speedup 1.0000x reference)
#include <cuda_runtime.h>
#include <cstdint>

typedef unsigned long long ull;

#define B_ 8
#define C_ 64
#define F_ 256
#define T_ 512
#define FT_ (F_*T_)                 /* 131072 */
#define NTHR_ 23
#define NPOSF 1048576.0

// ---------------- device scratch (static; no runtime allocation) ----------------
__device__ float  g_meanF[B_*C_*T_];     // mean over F  -> [B,C,T]
__device__ float  g_meanT[B_*C_*F_];     // mean over T  -> [B,C,F]
__device__ float  g_zt[B_*C_*T_];
__device__ float  g_zf[B_*C_*F_];
__device__ float  g_att[B_*F_*T_];
__device__ float  g_o[(size_t)B_*C_*F_*T_];   // 256 MB pre-BN activations
__device__ float  g_part[8192*128];           // per-CTA partial sum/sumsq
__device__ float  g_thr[NTHR_+1];
__device__ float  g_pw[64*24];                // prefix sums of wc2: pw[c*24+j]
__device__ float2 g_Wp[128*32];               // paired fused weights (channel pairs)
__device__ float2 g_bop[32];
__device__ float  g_scale[64];
__device__ float  g_shift[64];

// ---------------- f32x2 helpers ----------------
__device__ __forceinline__ ull pk(float lo, float hi) {
    ull r; asm("mov.b64 %0, {%1, %2};" : "=l"(r) : "f"(lo), "f"(hi)); return r;
}
__device__ __forceinline__ void fma2(ull &d, ull a, ull b) {
    asm("fma.rn.f32x2 %0, %1, %2, %3;" : "=l"(d) : "l"(a), "l"(b), "l"(d));
}
__device__ __forceinline__ float2 upk(ull v) {
    float2 r;
    r.x = __uint_as_float((unsigned)(v & 0xffffffffull));
    r.y = __uint_as_float((unsigned)(v >> 32));
    return r;
}

// ---------------- K0: prep tables ----------------
__global__ void k_prep(const float* __restrict__ wc2, const float* __restrict__ bc2,
                       const float* __restrict__ wo,  const float* __restrict__ bo) {
    int tid = threadIdx.x;  // 128
    if (tid == 0) {
        double cnt = 0.0;
        for (int i = 1; i <= NTHR_; i++) { cnt += (double)i / 300.0; g_thr[i-1] = (float)cnt; }
    }
    if (tid < 64) {
        int c = tid;
        float s = 0.f;
        g_pw[c*24 + 0] = 0.f;
        for (int j = 1; j <= NTHR_; j++) { s += wc2[c*NTHR_ + (j-1)]; g_pw[c*24 + j] = s; }
    }
    {
        int k = tid; // 0..127 : augmented weight W[k][c]
        for (int cp = 0; cp < 32; cp++) {
            int c0 = 2*cp, c1 = 2*cp + 1;
            float w0, w1v;
            if (k < 64) {
                w0  = wo[c0*128 + k] + wo[c0*128 + 64 + k] * bc2[k];
                w1v = wo[c1*128 + k] + wo[c1*128 + 64 + k] * bc2[k];
            } else {
                w0  = wo[c0*128 + k];
                w1v = wo[c1*128 + k];
            }
            g_Wp[k*32 + cp] = make_float2(w0, w1v);
        }
    }
    if (tid < 32) g_bop[tid] = make_float2(bo[2*tid], bo[2*tid+1]);
}

// ---------------- K1: means over F and over T per (b,c) plane ----------------
__global__ void k_reduce_means(const float* __restrict__ x) {
    int bc = blockIdx.x;                  // b*64 + c
    const float* plane = x + (size_t)bc * FT_;
    int w = threadIdx.x >> 5, lane = threadIdx.x & 31;
    __shared__ float colp[8][512];

    float4 cacc[4];
    #pragma unroll
    for (int it = 0; it < 4; it++) cacc[it] = make_float4(0.f, 0.f, 0.f, 0.f);

    for (int f = w; f < F_; f += 8) {
        const float4* row = (const float4*)(plane + (size_t)f * T_);
        float rsum = 0.f;
        #pragma unroll
        for (int it = 0; it < 4; it++) {
            float4 v = row[lane + 32*it];
            rsum += (v.x + v.y) + (v.z + v.w);
            cacc[it].x += v.x; cacc[it].y += v.y; cacc[it].z += v.z; cacc[it].w += v.w;
        }
        #pragma unroll
        for (int off = 16; off > 0; off >>= 1) rsum += __shfl_xor_sync(0xffffffffu, rsum, off);
        if (lane == 0) g_meanT[(size_t)bc * F_ + f] = rsum * (1.f / (float)T_);
    }
    #pragma unroll
    for (int it = 0; it < 4; it++) ((float4*)colp[w])[lane + 32*it] = cacc[it];
    __syncthreads();
    for (int t = threadIdx.x; t < T_; t += 256) {
        float s = 0.f;
        #pragma unroll
        for (int ww = 0; ww < 8; ww++) s += colp[ww][t];
        g_meanF[(size_t)bc * T_ + t] = s * (1.f / (float)F_);
    }
}

// ---------------- K2: channel MLP -> zt, zf ----------------
__global__ void k_mlp(const float* __restrict__ w1, const float* __restrict__ b1,
                      const float* __restrict__ w2, const float* __restrict__ b2) {
    int l = blockIdx.x;       // [0,512) -> T side, [512,768) -> F side
    int b = blockIdx.y;
    int c = threadIdx.x;      // 64 threads
    bool isT = (l < T_);
    int L  = isT ? T_ : F_;
    int ll = isT ? l : l - T_;
    const float* src = isT ? g_meanF : g_meanT;
    float* dst       = isT ? g_zt    : g_zf;

    __shared__ float zs[64];
    __shared__ float hs[8];
    zs[c] = src[((size_t)b*64 + c) * L + ll];
    __syncthreads();
    if (c < 5) {
        float a = b1[c];
        #pragma unroll 8
        for (int i = 0; i < 64; i++) a += w1[c*64 + i] * zs[i];
        hs[c] = fmaxf(a, 0.f);
    }
    __syncthreads();
    float v = b2[c];
    #pragma unroll
    for (int j = 0; j < 5; j++) v += w2[c*5 + j] * hs[j];
    dst[((size_t)b*64 + c) * L + ll] = 1.f / (1.f + expf(-v));
}

// ---------------- K3: att_map[b,f,t] = sum_c wc[c]*zf[b,c,f]*zt[b,c,t] + bc ----------------
__global__ void k_attmap(const float* __restrict__ wc, const float* __restrict__ bc) {
    int b = blockIdx.y;
    int f0 = blockIdx.x * 8;
    int tid = threadIdx.x;       // 256
    int t0 = tid * 2;
    __shared__ float wcz[8][64];
    for (int i = tid; i < 512; i += 256) {
        int fi = i >> 6, c = i & 63;
        wcz[fi][c] = wc[c] * g_zf[((size_t)b*64 + c) * F_ + f0 + fi];
    }
    __syncthreads();
    float bcv = bc[0];
    float2 acc[8];
    #pragma unroll
    for (int fi = 0; fi < 8; fi++) acc[fi] = make_float2(bcv, bcv);
    const float* ztb = g_zt + (size_t)b * 64 * T_;
    for (int c = 0; c < 64; c++) {
        float2 z2 = *(const float2*)(ztb + (size_t)c * T_ + t0);
        #pragma unroll
        for (int fi = 0; fi < 8; fi++) {
            acc[fi].x += wcz[fi][c] * z2.x;
            acc[fi].y += wcz[fi][c] * z2.y;
        }
    }
    #pragma unroll
    for (int fi = 0; fi < 8; fi++)
        *(float2*)&g_att[((size_t)b*F_ + f0 + fi) * T_ + t0] = acc[fi];
}

// ---------------- K4: fused augmented GEMM + BN partial stats ----------------
// CTA 128 threads, tile 64 channels x 128 t. K=128 augmented inputs.
#define K4_SMEM_FLOATS (16384 + 8192 + 1536 + 32)
#define K4_SMEM_BYTES  (K4_SMEM_FLOATS * 4)

__global__ void __launch_bounds__(128, 2) k_main(const float* __restrict__ x) {
    extern __shared__ float sm[];
    float*  Xa   = sm;                      // [128][128]
    float2* WpS  = (float2*)(sm + 16384);   // [128*32]
    float*  pwS  = sm + 16384 + 8192;       // [64*24]
    float*  thrS = pwS + 1536;              // [32]

    const int tid = threadIdx.x;
    const int tt = blockIdx.x, f = blockIdx.y, b = blockIdx.z;
    const int t0 = tt * 128;

    for (int i = tid; i < 4096; i += 128) WpS[i] = g_Wp[i];
    for (int i = tid; i < 1536; i += 128) pwS[i] = g_pw[i];
    if (tid < NTHR_) thrS[tid] = g_thr[tid];

    const float* xb = x + ((size_t)b*64*256 + f) * 512 + t0;
    for (int i = tid; i < 2048; i += 128) {
        int c = i >> 5, q = i & 31;
        *(float4*)&Xa[c*128 + q*4] = *(const float4*)(xb + (size_t)c*FT_ + q*4);
    }
    float a = g_att[((size_t)b*F_ + f) * T_ + t0 + tid];
    __syncthreads();

    // thresholded prefix index for this t column
    int Kc = 0;
    #pragma unroll
    for (int i = 0; i < NTHR_; i++) Kc += (a > thrS[i]) ? 1 : 0;
    // augmented rows 64..127
    #pragma unroll 8
    for (int k = 0; k < 64; k++)
        Xa[(64+k)*128 + tid] = a * pwS[k*24 + Kc] * Xa[k*128 + tid];
    __syncthreads();

    const int cg = tid & 7;   // channel group: pairs cg*4..cg*4+3 -> channels cg*8..cg*8+7
    const int tg = tid >> 3;  // t group: t = tg*8..tg*8+7

    ull acc[4][8];
    #pragma unroll
    for (int p = 0; p < 4; p++) {
        float2 bp = g_bop[cg*4 + p];
        ull bi = pk(bp.x, bp.y);
        #pragma unroll
        for (int j = 0; j < 8; j++) acc[p][j] = bi;
    }

    #pragma unroll 2
    for (int k = 0; k < 128; k++) {
        float4 x0 = *(const float4*)&Xa[k*128 + tg*8];
        float4 x1 = *(const float4*)&Xa[k*128 + tg*8 + 4];
        ull xd[8];
        xd[0] = pk(x0.x, x0.x); xd[1] = pk(x0.y, x0.y);
        xd[2] = pk(x0.z, x0.z); xd[3] = pk(x0.w, x0.w);
        xd[4] = pk(x1.x, x1.x); xd[5] = pk(x1.y, x1.y);
        xd[6] = pk(x1.z, x1.z); xd[7] = pk(x1.w, x1.w);
        const float2* wr = &WpS[k*32 + cg*4];
        #pragma unroll
        for (int p = 0; p < 4; p++) {
            float2 w = wr[p];
            ull wp = pk(w.x, w.y);
            #pragma unroll
            for (int j = 0; j < 8; j++) fma2(acc[p][j], wp, xd[j]);
        }
    }
    __syncthreads();   // done reading Xa; smem reused for reduction

    float* Ssum = sm;          // [16][64]
    float* Ssq  = sm + 1024;   // [16][64]
    float sum8[8], sq8[8];
    float* ob = g_o + ((size_t)b*64*256 + f) * 512 + t0 + tg*8;
    #pragma unroll
    for (int p = 0; p < 4; p++) {
        float lo[8], hi[8];
        #pragma unroll
        for (int j = 0; j < 8; j++) { float2 v = upk(acc[p][j]); lo[j] = v.x; hi[j] = v.y; }
        int c0 = cg*8 + 2*p;
        *(float4*)(ob + (size_t)c0*FT_)       = make_float4(lo[0],lo[1],lo[2],lo[3]);
        *(float4*)(ob + (size_t)c0*FT_ + 4)   = make_float4(lo[4],lo[5],lo[6],lo[7]);
        *(float4*)(ob + (size_t)(c0+1)*FT_)     = make_float4(hi[0],hi[1],hi[2],hi[3]);
        *(float4*)(ob + (size_t)(c0+1)*FT_ + 4) = make_float4(hi[4],hi[5],hi[6],hi[7]);
        float s0=0.f,q0=0.f,s1=0.f,q1=0.f;
        #pragma unroll
        for (int j = 0; j < 8; j++) { s0 += lo[j]; q0 += lo[j]*lo[j]; s1 += hi[j]; q1 += hi[j]*hi[j]; }
        sum8[2*p] = s0; sq8[2*p] = q0; sum8[2*p+1] = s1; sq8[2*p+1] = q1;
    }
    #pragma unroll
    for (int cc = 0; cc < 8; cc++) {
        Ssum[tg*64 + cg*8 + cc] = sum8[cc];
        Ssq [tg*64 + cg*8 + cc] = sq8[cc];
    }
    __syncthreads();
    int cta = ((b*256 + f) << 2) + tt;
    if (tid < 64) {
        float s = 0.f;
        #pragma unroll
        for (int g = 0; g < 16; g++) s += Ssum[g*64 + tid];
        g_part[(size_t)cta*128 + tid] = s;
    } else {
        int c = tid - 64;
        float s = 0.f;
        #pragma unroll
        for (int g = 0; g < 16; g++) s += Ssq[g*64 + c];
        g_part[(size_t)cta*128 + 64 + c] = s;
    }
}

// ---------------- K5: reduce partials -> scale/shift (deterministic, double) ----------------
__global__ void k_stats(const float* __restrict__ gamma, const float* __restrict__ beta) {
    __shared__ double ds[8][64];
    __shared__ double dq[8][64];
    int g = threadIdx.x >> 6;   // 0..7
    int c = threadIdx.x & 63;
    double s = 0.0, q = 0.0;
    for (int i = g; i < 8192; i += 8) {
        s += (double)g_part[(size_t)i*128 + c];
        q += (double)g_part[(size_t)i*128 + 64 + c];
    }
    ds[g][c] = s; dq[g][c] = q;
    __syncthreads();
    if (threadIdx.x < 64) {
        double S = 0.0, Q = 0.0;
        #pragma unroll
        for (int i = 0; i < 8; i++) { S += ds[i][c]; Q += dq[i][c]; }
        double mu  = S / NPOSF;
        double var = Q / NPOSF - mu * mu;
        float sc = gamma[c] * (float)(1.0 / sqrt(var + 1e-5));
        g_scale[c] = sc;
        g_shift[c] = beta[c] - (float)mu * sc;
    }
}

// ---------------- K6: normalize + ReLU streaming ----------------
__global__ void k_norm(float* __restrict__ out) {
    __shared__ float sc[64], sh[64];
    if (threadIdx.x < 64) { sc[threadIdx.x] = g_scale[threadIdx.x]; sh[threadIdx.x] = g_shift[threadIdx.x]; }
    __syncthreads();
    const size_t n4 = (size_t)B_ * C_ * FT_ / 4;   // 16777216
    const float4* src = (const float4*)g_o;
    float4* dst = (float4*)out;
    for (size_t i = (size_t)blockIdx.x * blockDim.x + threadIdx.x; i < n4;
         i += (size_t)gridDim.x * blockDim.x) {
        float4 v = src[i];
        int c = (int)(i >> 15) & 63;   // FT_/4 = 32768 = 2^15
        float s = sc[c], t = sh[c];
        v.x = fmaxf(fmaf(v.x, s, t), 0.f);
        v.y = fmaxf(fmaf(v.y, s, t), 0.f);
        v.z = fmaxf(fmaf(v.z, s, t), 0.f);
        v.w = fmaxf(fmaf(v.w, s, t), 0.f);
        dst[i] = v;
    }
}

// ---------------- launch ----------------
extern "C" void kernel_launch(void* const* d_in, const int* in_sizes, int n_in,
                              void* d_out, int out_size) {
    const float* x     = (const float*)d_in[0];
    const float* w1    = (const float*)d_in[1];
    const float* b1    = (const float*)d_in[2];
    const float* w2    = (const float*)d_in[3];
    const float* b2    = (const float*)d_in[4];
    const float* wc    = (const float*)d_in[5];
    const float* bc    = (const float*)d_in[6];
    const float* wc2   = (const float*)d_in[7];
    const float* bc2   = (const float*)d_in[8];
    const float* wo    = (const float*)d_in[9];
    const float* bo    = (const float*)d_in[10];
    const float* gamma = (const float*)d_in[11];
    const float* beta  = (const float*)d_in[12];
    float* out = (float*)d_out;

    cudaFuncSetAttribute(k_main, cudaFuncAttributeMaxDynamicSharedMemorySize, K4_SMEM_BYTES);

    k_prep<<<1, 128>>>(wc2, bc2, wo, bo);
    k_reduce_means<<<B_*C_, 256>>>(x);
    k_mlp<<<dim3(768, B_), 64>>>(w1, b1, w2, b2);
    k_attmap<<<dim3(F_/8, B_), 256>>>(wc, bc);
    k_main<<<dim3(4, F_, B_), 128, K4_SMEM_BYTES>>>(x);
    k_stats<<<1, 512>>>(gamma, beta);
    k_norm<<<4096, 256>>>(out);
}

// round 4
// speedup vs baseline: 1.2782x; 1.2782x over previous
#include <cuda_runtime.h>
#include <cuda_bf16.h>
#include <cstdint>

#define B_ 8
#define C_ 64
#define F_ 256
#define T_ 512
#define FT_ (F_*T_)                 /* 131072 */
#define NTHR_ 23
#define NPOSF 1048576.0

// ---------------- device scratch (static; no runtime allocation) ----------------
__device__ float  g_meanF[B_*C_*T_];
__device__ float  g_meanT[B_*C_*F_];
__device__ float  g_zt[B_*C_*T_];
__device__ float  g_zf[B_*C_*F_];
__device__ float  g_att[B_*F_*T_];
__device__ float  g_o[(size_t)B_*C_*F_*T_];   // 256 MB pre-BN activations
__device__ float  g_part[8192*128];
__device__ float  g_thr[32];
__device__ float  g_pw[64*24];                // prefix sums of wc2
__device__ __align__(16) unsigned short g_Wbh[64*136];  // W bf16 hi, padded row-major [c][k]
__device__ __align__(16) unsigned short g_Wbl[64*136];  // W bf16 lo
__device__ float  g_scale[64];
__device__ float  g_shift[64];

__device__ __forceinline__ uint32_t smem_u32(const void* p) {
    uint32_t a;
    asm("{ .reg .u64 t; cvta.to.shared.u64 t, %1; cvt.u32.u64 %0, t; }" : "=r"(a) : "l"(p));
    return a;
}
__device__ __forceinline__ void ldsm_x4(uint32_t* r, uint32_t addr) {
    asm volatile("ldmatrix.sync.aligned.m8n8.x4.shared.b16 {%0,%1,%2,%3}, [%4];"
        : "=r"(r[0]), "=r"(r[1]), "=r"(r[2]), "=r"(r[3]) : "r"(addr));
}
__device__ __forceinline__ void mma16816(float* d, const uint32_t* a, const uint32_t* b) {
    asm volatile("mma.sync.aligned.m16n8k16.row.col.f32.bf16.bf16.f32 "
        "{%0,%1,%2,%3}, {%4,%5,%6,%7}, {%8,%9}, {%0,%1,%2,%3};"
        : "+f"(d[0]), "+f"(d[1]), "+f"(d[2]), "+f"(d[3])
        : "r"(a[0]), "r"(a[1]), "r"(a[2]), "r"(a[3]), "r"(b[0]), "r"(b[1]));
}

// ---------------- K0: prep tables + padded bf16 W hi/lo ----------------
__global__ void k_prep(const float* __restrict__ wc2, const float* __restrict__ bc2,
                       const float* __restrict__ wo) {
    int tid = threadIdx.x;  // 128
    if (tid == 0) {
        double cnt = 0.0;
        for (int i = 1; i <= NTHR_; i++) { cnt += (double)i / 300.0; g_thr[i-1] = (float)cnt; }
    }
    if (tid < 64) {
        int c = tid;
        float s = 0.f;
        g_pw[c*24 + 0] = 0.f;
        for (int j = 1; j <= NTHR_; j++) { s += wc2[c*NTHR_ + (j-1)]; g_pw[c*24 + j] = s; }
    }
    int k = tid;  // 0..127 : augmented weight W[c][k]
    for (int c = 0; c < 64; c++) {
        float w;
        if (k < 64) w = wo[c*128 + k] + wo[c*128 + 64 + k] * bc2[k];
        else        w = wo[c*128 + k];
        __nv_bfloat16 hi = __float2bfloat16_rn(w);
        __nv_bfloat16 lo = __float2bfloat16_rn(w - __bfloat162float(hi));
        g_Wbh[c*136 + k] = __bfloat16_as_ushort(hi);
        g_Wbl[c*136 + k] = __bfloat16_as_ushort(lo);
    }
}

// ---------------- K1: means over F and over T per (b,c) plane ----------------
__global__ void k_reduce_means(const float* __restrict__ x) {
    int bc = blockIdx.x;
    const float* plane = x + (size_t)bc * FT_;
    int w = threadIdx.x >> 5, lane = threadIdx.x & 31;
    __shared__ float colp[8][512];

    float4 cacc[4];
    #pragma unroll
    for (int it = 0; it < 4; it++) cacc[it] = make_float4(0.f, 0.f, 0.f, 0.f);

    for (int f = w; f < F_; f += 8) {
        const float4* row = (const float4*)(plane + (size_t)f * T_);
        float rsum = 0.f;
        #pragma unroll
        for (int it = 0; it < 4; it++) {
            float4 v = row[lane + 32*it];
            rsum += (v.x + v.y) + (v.z + v.w);
            cacc[it].x += v.x; cacc[it].y += v.y; cacc[it].z += v.z; cacc[it].w += v.w;
        }
        #pragma unroll
        for (int off = 16; off > 0; off >>= 1) rsum += __shfl_xor_sync(0xffffffffu, rsum, off);
        if (lane == 0) g_meanT[(size_t)bc * F_ + f] = rsum * (1.f / (float)T_);
    }
    #pragma unroll
    for (int it = 0; it < 4; it++) ((float4*)colp[w])[lane + 32*it] = cacc[it];
    __syncthreads();
    for (int t = threadIdx.x; t < T_; t += 256) {
        float s = 0.f;
        #pragma unroll
        for (int ww = 0; ww < 8; ww++) s += colp[ww][t];
        g_meanF[(size_t)bc * T_ + t] = s * (1.f / (float)F_);
    }
}

// ---------------- K2: channel MLP -> zt, zf ----------------
__global__ void k_mlp(const float* __restrict__ w1, const float* __restrict__ b1,
                      const float* __restrict__ w2, const float* __restrict__ b2) {
    int l = blockIdx.x;
    int b = blockIdx.y;
    int c = threadIdx.x;
    bool isT = (l < T_);
    int L  = isT ? T_ : F_;
    int ll = isT ? l : l - T_;
    const float* src = isT ? g_meanF : g_meanT;
    float* dst       = isT ? g_zt    : g_zf;

    __shared__ float zs[64];
    __shared__ float hs[8];
    zs[c] = src[((size_t)b*64 + c) * L + ll];
    __syncthreads();
    if (c < 5) {
        float a = b1[c];
        #pragma unroll 8
        for (int i = 0; i < 64; i++) a += w1[c*64 + i] * zs[i];
        hs[c] = fmaxf(a, 0.f);
    }
    __syncthreads();
    float v = b2[c];
    #pragma unroll
    for (int j = 0; j < 5; j++) v += w2[c*5 + j] * hs[j];
    dst[((size_t)b*64 + c) * L + ll] = 1.f / (1.f + expf(-v));
}

// ---------------- K3: att_map ----------------
__global__ void k_attmap(const float* __restrict__ wc, const float* __restrict__ bc) {
    int b = blockIdx.y;
    int f0 = blockIdx.x * 8;
    int tid = threadIdx.x;
    int t0 = tid * 2;
    __shared__ float wcz[8][64];
    for (int i = tid; i < 512; i += 256) {
        int fi = i >> 6, c = i & 63;
        wcz[fi][c] = wc[c] * g_zf[((size_t)b*64 + c) * F_ + f0 + fi];
    }
    __syncthreads();
    float bcv = bc[0];
    float2 acc[8];
    #pragma unroll
    for (int fi = 0; fi < 8; fi++) acc[fi] = make_float2(bcv, bcv);
    const float* ztb = g_zt + (size_t)b * 64 * T_;
    for (int c = 0; c < 64; c++) {
        float2 z2 = *(const float2*)(ztb + (size_t)c * T_ + t0);
        #pragma unroll
        for (int fi = 0; fi < 8; fi++) {
            acc[fi].x += wcz[fi][c] * z2.x;
            acc[fi].y += wcz[fi][c] * z2.y;
        }
    }
    #pragma unroll
    for (int fi = 0; fi < 8; fi++)
        *(float2*)&g_att[((size_t)b*F_ + f0 + fi) * T_ + t0] = acc[fi];
}

// ---------------- K4: HMMA augmented GEMM + BN partial stats ----------------
// Tile: M=128 (t) x N=64 (c), K=128. bf16 hi/lo split, 3 mma passes.
// smem byte offsets (row stride 272B = 136 bf16):
#define AH_OFF 0u
#define AL_OFF 34816u
#define WH_OFF 69632u
#define WL_OFF 87040u
#define PW_OFF 104448u
#define THR_OFF 110592u
#define BOS_OFF 110720u
#define K4_SMEM 110976

__global__ void __launch_bounds__(256, 2) k_main(const float* __restrict__ x,
                                                 const float* __restrict__ bo) {
    extern __shared__ char sm[];
    const uint32_t s0 = smem_u32(sm);
    const int tid = threadIdx.x;
    const int lane = tid & 31;
    const int wid = tid >> 5;
    const int tt = blockIdx.x, f = blockIdx.y, b = blockIdx.z;
    const int t0 = tt * 128;

    // ---- stage W hi/lo (17408B each), pw, thr, bos ----
    {
        const uint4* wh = (const uint4*)g_Wbh;
        const uint4* wl = (const uint4*)g_Wbl;
        uint4* dh = (uint4*)(sm + WH_OFF);
        uint4* dl = (uint4*)(sm + WL_OFF);
        for (int i = tid; i < 1088; i += 256) { dh[i] = wh[i]; dl[i] = wl[i]; }
        float* pwd = (float*)(sm + PW_OFF);
        for (int i = tid; i < 1536; i += 256) pwd[i] = g_pw[i];
        if (tid < 32) ((float*)(sm + THR_OFF))[tid] = g_thr[tid];
        if (tid < 64) ((float*)(sm + BOS_OFF))[tid] = bo[tid];
    }
    __syncthreads();

    // ---- build augmented A tile (bf16 hi/lo), row = t, cols k=0..127 ----
    {
        const int t   = tid & 127;
        const int ch  = (tid >> 7) * 32;     // this thread covers channels ch..ch+31
        float a = g_att[((size_t)b*F_ + f) * T_ + t0 + t];
        const float* thrS = (const float*)(sm + THR_OFF);
        int Kc = 0;
        #pragma unroll
        for (int i = 0; i < NTHR_; i++) Kc += (a > thrS[i]) ? 1 : 0;
        const float* pwS = (const float*)(sm + PW_OFF) + Kc;

        const float* xp = x + ((size_t)b*64*256 + f) * 512 + t0 + t;
        char* rowH = sm + AH_OFF + (unsigned)t * 272u;
        char* rowL = sm + AL_OFF + (unsigned)t * 272u;
        #pragma unroll
        for (int c4 = 0; c4 < 32; c4 += 4) {
            int c = ch + c4;
            float v[4], av[4];
            #pragma unroll
            for (int j = 0; j < 4; j++) v[j] = __ldg(xp + (size_t)(c + j) * FT_);
            #pragma unroll
            for (int j = 0; j < 4; j++) av[j] = a * pwS[(c + j) * 24] * v[j];
            unsigned short h[4], l[4], ah[4], al[4];
            #pragma unroll
            for (int j = 0; j < 4; j++) {
                __nv_bfloat16 hb = __float2bfloat16_rn(v[j]);
                h[j] = __bfloat16_as_ushort(hb);
                l[j] = __bfloat16_as_ushort(__float2bfloat16_rn(v[j] - __bfloat162float(hb)));
                __nv_bfloat16 ab = __float2bfloat16_rn(av[j]);
                ah[j] = __bfloat16_as_ushort(ab);
                al[j] = __bfloat16_as_ushort(__float2bfloat16_rn(av[j] - __bfloat162float(ab)));
            }
            uint2 ph  = make_uint2((unsigned)h[0]  | ((unsigned)h[1]  << 16), (unsigned)h[2]  | ((unsigned)h[3]  << 16));
            uint2 pl  = make_uint2((unsigned)l[0]  | ((unsigned)l[1]  << 16), (unsigned)l[2]  | ((unsigned)l[3]  << 16));
            uint2 pah = make_uint2((unsigned)ah[0] | ((unsigned)ah[1] << 16), (unsigned)ah[2] | ((unsigned)ah[3] << 16));
            uint2 pal = make_uint2((unsigned)al[0] | ((unsigned)al[1] << 16), (unsigned)al[2] | ((unsigned)al[3] << 16));
            *(uint2*)(rowH + c*2)        = ph;
            *(uint2*)(rowL + c*2)        = pl;
            *(uint2*)(rowH + 128 + c*2)  = pah;   // cols 64..127 = augmented
            *(uint2*)(rowL + 128 + c*2)  = pal;
        }
    }
    __syncthreads();

    // ---- warp-level HMMA: warp tile 32 (t) x 32 (c) ----
    const int wm = wid & 3;        // m block (t):  rows wm*32..+31
    const int wn = wid >> 2;       // n block (c):  cols wn*32..+31
    const int quad = lane >> 3, r8 = lane & 7;

    // A ldsm.x4 addresses: mat0:(r,klo) mat1:(r+8,klo) mat2:(r,khi) mat3:(r+8,khi)
    const int arow = (quad & 1) ? 8 : 0;
    const int akof = (quad & 2) ? 16 : 0;   // bytes (+8 bf16)
    uint32_t aH0 = s0 + AH_OFF + (unsigned)(wm*32 + arow + r8) * 272u + akof;
    uint32_t aH1 = aH0 + 16u * 272u;
    // B ldsm.x4: mat0:b0(n8 blk even) mat1:b1(even) mat2:b0(odd) mat3:b1(odd)
    const int brow = (quad & 2) ? 8 : 0;
    const int bkof = (quad & 1) ? 16 : 0;
    uint32_t bH0 = s0 + WH_OFF + (unsigned)(wn*32 + brow + r8) * 272u + bkof;
    uint32_t bH1 = bH0 + 16u * 272u;

    float acc[2][4][4];
    #pragma unroll
    for (int ms = 0; ms < 2; ms++)
        #pragma unroll
        for (int nb = 0; nb < 4; nb++)
            #pragma unroll
            for (int e = 0; e < 4; e++) acc[ms][nb][e] = 0.f;

    #pragma unroll 2
    for (int ks = 0; ks < 8; ks++) {
        const uint32_t ko = (unsigned)ks * 32u;
        uint32_t ah[2][4], al[2][4], bh[2][4], bl[2][4];
        ldsm_x4(ah[0], aH0 + ko);
        ldsm_x4(ah[1], aH1 + ko);
        ldsm_x4(al[0], aH0 + AL_OFF - AH_OFF + ko);
        ldsm_x4(al[1], aH1 + AL_OFF - AH_OFF + ko);
        ldsm_x4(bh[0], bH0 + ko);
        ldsm_x4(bh[1], bH1 + ko);
        ldsm_x4(bl[0], bH0 + (WL_OFF - WH_OFF) + ko);
        ldsm_x4(bl[1], bH1 + (WL_OFF - WH_OFF) + ko);
        #pragma unroll
        for (int ms = 0; ms < 2; ms++) {
            #pragma unroll
            for (int nb = 0; nb < 4; nb++) {
                const uint32_t* bhp = &bh[nb >> 1][(nb & 1) * 2];
                const uint32_t* blp = &bl[nb >> 1][(nb & 1) * 2];
                mma16816(acc[ms][nb], ah[ms], bhp);
                mma16816(acc[ms][nb], ah[ms], blp);
                mma16816(acc[ms][nb], al[ms], bhp);
            }
        }
    }
    __syncthreads();

    // ---- write acc to smem transpose buffer stat[c][t], stride 132 ----
    float* stat = (float*)sm;    // reuse AH/AL region: 64*132*4 = 33792 B
    {
        const int r = lane >> 2, nq = lane & 3;
        #pragma unroll
        for (int ms = 0; ms < 2; ms++) {
            #pragma unroll
            for (int nb = 0; nb < 4; nb++) {
                int tl = wm*32 + ms*16 + r;
                int cc = wn*32 + nb*8 + 2*nq;
                stat[(cc  )*132 + tl    ] = acc[ms][nb][0];
                stat[(cc+1)*132 + tl    ] = acc[ms][nb][1];
                stat[(cc  )*132 + tl + 8] = acc[ms][nb][2];
                stat[(cc+1)*132 + tl + 8] = acc[ms][nb][3];
            }
        }
    }
    __syncthreads();

    // ---- coalesced g_o writes + BN partials ----
    float* ssum = (float*)(sm + WH_OFF);          // [64][4]
    float* ssq  = (float*)(sm + WH_OFF + 1024);   // [64][4]
    {
        const int c = tid >> 2, q = tid & 3;
        const float bos = ((const float*)(sm + BOS_OFF))[c];
        const float* row = stat + c*132 + q*32;
        float* ob = g_o + ((size_t)b*64*256 + (size_t)c*256 + f) * 512 + t0 + q*32;
        float s = 0.f, sq = 0.f;
        #pragma unroll
        for (int i = 0; i < 8; i++) {
            float4 v = *(const float4*)(row + i*4);
            v.x += bos; v.y += bos; v.z += bos; v.w += bos;
            s  += (v.x + v.y) + (v.z + v.w);
            sq += (v.x*v.x + v.y*v.y) + (v.z*v.z + v.w*v.w);
            *(float4*)(ob + i*4) = v;
        }
        ssum[c*4 + q] = s;
        ssq [c*4 + q] = sq;
    }
    __syncthreads();
    if (tid < 64) {
        int cta = ((b*256 + f) << 2) + tt;
        float s  = ssum[tid*4] + ssum[tid*4+1] + ssum[tid*4+2] + ssum[tid*4+3];
        float sq = ssq [tid*4] + ssq [tid*4+1] + ssq [tid*4+2] + ssq [tid*4+3];
        g_part[(size_t)cta*128 + tid]      = s;
        g_part[(size_t)cta*128 + 64 + tid] = sq;
    }
}

// ---------------- K5: reduce partials -> scale/shift ----------------
__global__ void k_stats(const float* __restrict__ gamma, const float* __restrict__ beta) {
    __shared__ double ds[8][64];
    __shared__ double dq[8][64];
    int g = threadIdx.x >> 6;
    int c = threadIdx.x & 63;
    double s = 0.0, q = 0.0;
    for (int i = g; i < 8192; i += 8) {
        s += (double)g_part[(size_t)i*128 + c];
        q += (double)g_part[(size_t)i*128 + 64 + c];
    }
    ds[g][c] = s; dq[g][c] = q;
    __syncthreads();
    if (threadIdx.x < 64) {
        double S = 0.0, Q = 0.0;
        #pragma unroll
        for (int i = 0; i < 8; i++) { S += ds[i][c]; Q += dq[i][c]; }
        double mu  = S / NPOSF;
        double var = Q / NPOSF - mu * mu;
        float sc = gamma[c] * (float)(1.0 / sqrt(var + 1e-5));
        g_scale[c] = sc;
        g_shift[c] = beta[c] - (float)mu * sc;
    }
}

// ---------------- K6: normalize + ReLU streaming ----------------
__global__ void k_norm(float* __restrict__ out) {
    __shared__ float sc[64], sh[64];
    if (threadIdx.x < 64) { sc[threadIdx.x] = g_scale[threadIdx.x]; sh[threadIdx.x] = g_shift[threadIdx.x]; }
    __syncthreads();
    const size_t n4 = (size_t)B_ * C_ * FT_ / 4;
    const float4* src = (const float4*)g_o;
    float4* dst = (float4*)out;
    for (size_t i = (size_t)blockIdx.x * blockDim.x + threadIdx.x; i < n4;
         i += (size_t)gridDim.x * blockDim.x) {
        float4 v = src[i];
        int c = (int)(i >> 15) & 63;
        float s = sc[c], t = sh[c];
        v.x = fmaxf(fmaf(v.x, s, t), 0.f);
        v.y = fmaxf(fmaf(v.y, s, t), 0.f);
        v.z = fmaxf(fmaf(v.z, s, t), 0.f);
        v.w = fmaxf(fmaf(v.w, s, t), 0.f);
        dst[i] = v;
    }
}

// ---------------- launch ----------------
extern "C" void kernel_launch(void* const* d_in, const int* in_sizes, int n_in,
                              void* d_out, int out_size) {
    const float* x     = (const float*)d_in[0];
    const float* w1    = (const float*)d_in[1];
    const float* b1    = (const float*)d_in[2];
    const float* w2    = (const float*)d_in[3];
    const float* b2    = (const float*)d_in[4];
    const float* wc    = (const float*)d_in[5];
    const float* bc    = (const float*)d_in[6];
    const float* wc2   = (const float*)d_in[7];
    const float* bc2   = (const float*)d_in[8];
    const float* wo    = (const float*)d_in[9];
    const float* bo    = (const float*)d_in[10];
    const float* gamma = (const float*)d_in[11];
    const float* beta  = (const float*)d_in[12];
    float* out = (float*)d_out;

    cudaFuncSetAttribute(k_main, cudaFuncAttributeMaxDynamicSharedMemorySize, K4_SMEM);

    k_prep<<<1, 128>>>(wc2, bc2, wo);
    k_reduce_means<<<B_*C_, 256>>>(x);
    k_mlp<<<dim3(768, B_), 64>>>(w1, b1, w2, b2);
    k_attmap<<<dim3(F_/8, B_), 256>>>(wc, bc);
    k_main<<<dim3(4, F_, B_), 256, K4_SMEM>>>(x, bo);
    k_stats<<<1, 512>>>(gamma, beta);
    k_norm<<<4096, 256>>>(out);
}

// round 5
// speedup vs baseline: 1.8490x; 1.4466x over previous
#include <cuda_runtime.h>
#include <cuda_bf16.h>
#include <cstdint>

#define B_ 8
#define C_ 64
#define F_ 256
#define T_ 512
#define FT_ (F_*T_)                 /* 131072 */
#define NTHR_ 23
#define NPOSF 1048576.0

// ---------------- device scratch (static; no runtime allocation) ----------------
__device__ float  g_meanF[B_*C_*T_];
__device__ float  g_meanT[B_*C_*F_];
__device__ float  g_zt[B_*C_*T_];
__device__ float  g_zf[B_*C_*F_];
__device__ float  g_att[B_*F_*T_];
__device__ float  g_o[(size_t)B_*C_*F_*T_];   // 256 MB pre-BN activations
__device__ float  g_part[8192*128];
__device__ float  g_part2[128*128];
__device__ float  g_thr[32];
__device__ float  g_pw[64*24];                // prefix sums of wc2
__device__ __align__(16) unsigned short g_Wbh[64*136];  // W bf16 hi, padded row-major [c][k]
__device__ __align__(16) unsigned short g_Wbl[64*136];  // W bf16 lo
__device__ float  g_scale[64];
__device__ float  g_shift[64];

__device__ __forceinline__ uint32_t smem_u32(const void* p) {
    uint32_t a;
    asm("{ .reg .u64 t; cvta.to.shared.u64 t, %1; cvt.u32.u64 %0, t; }" : "=r"(a) : "l"(p));
    return a;
}
__device__ __forceinline__ void ldsm_x4(uint32_t* r, uint32_t addr) {
    asm volatile("ldmatrix.sync.aligned.m8n8.x4.shared.b16 {%0,%1,%2,%3}, [%4];"
        : "=r"(r[0]), "=r"(r[1]), "=r"(r[2]), "=r"(r[3]) : "r"(addr));
}
__device__ __forceinline__ void mma16816(float* d, const uint32_t* a, const uint32_t* b) {
    asm volatile("mma.sync.aligned.m16n8k16.row.col.f32.bf16.bf16.f32 "
        "{%0,%1,%2,%3}, {%4,%5,%6,%7}, {%8,%9}, {%0,%1,%2,%3};"
        : "+f"(d[0]), "+f"(d[1]), "+f"(d[2]), "+f"(d[3])
        : "r"(a[0]), "r"(a[1]), "r"(a[2]), "r"(a[3]), "r"(b[0]), "r"(b[1]));
}

// ---------------- K1: means over F/T per plane; block 512 = table prep ----------------
__global__ void k_reduce_prep(const float* __restrict__ x,
                              const float* __restrict__ wc2, const float* __restrict__ bc2,
                              const float* __restrict__ wo) {
    if (blockIdx.x == 512) {
        int tid = threadIdx.x;  // 256
        if (tid == 0) {
            double cnt = 0.0;
            for (int i = 1; i <= NTHR_; i++) { cnt += (double)i / 300.0; g_thr[i-1] = (float)cnt; }
        }
        if (tid < 64) {
            int c = tid;
            float s = 0.f;
            g_pw[c*24 + 0] = 0.f;
            for (int j = 1; j <= NTHR_; j++) { s += wc2[c*NTHR_ + (j-1)]; g_pw[c*24 + j] = s; }
        }
        if (tid < 128) {
            int k = tid;  // augmented weight W[c][k]
            for (int c = 0; c < 64; c++) {
                float w;
                if (k < 64) w = wo[c*128 + k] + wo[c*128 + 64 + k] * bc2[k];
                else        w = wo[c*128 + k];
                __nv_bfloat16 hi = __float2bfloat16_rn(w);
                __nv_bfloat16 lo = __float2bfloat16_rn(w - __bfloat162float(hi));
                g_Wbh[c*136 + k] = __bfloat16_as_ushort(hi);
                g_Wbl[c*136 + k] = __bfloat16_as_ushort(lo);
            }
        }
        return;
    }
    int bc = blockIdx.x;
    const float* plane = x + (size_t)bc * FT_;
    int w = threadIdx.x >> 5, lane = threadIdx.x & 31;
    __shared__ float colp[8][512];

    float4 cacc[4];
    #pragma unroll
    for (int it = 0; it < 4; it++) cacc[it] = make_float4(0.f, 0.f, 0.f, 0.f);

    for (int f = w; f < F_; f += 8) {
        const float4* row = (const float4*)(plane + (size_t)f * T_);
        float rsum = 0.f;
        #pragma unroll
        for (int it = 0; it < 4; it++) {
            float4 v = row[lane + 32*it];
            rsum += (v.x + v.y) + (v.z + v.w);
            cacc[it].x += v.x; cacc[it].y += v.y; cacc[it].z += v.z; cacc[it].w += v.w;
        }
        #pragma unroll
        for (int off = 16; off > 0; off >>= 1) rsum += __shfl_xor_sync(0xffffffffu, rsum, off);
        if (lane == 0) g_meanT[(size_t)bc * F_ + f] = rsum * (1.f / (float)T_);
    }
    #pragma unroll
    for (int it = 0; it < 4; it++) ((float4*)colp[w])[lane + 32*it] = cacc[it];
    __syncthreads();
    for (int t = threadIdx.x; t < T_; t += 256) {
        float s = 0.f;
        #pragma unroll
        for (int ww = 0; ww < 8; ww++) s += colp[ww][t];
        g_meanF[(size_t)bc * T_ + t] = s * (1.f / (float)F_);
    }
}

// ---------------- K2: channel MLP -> zt, zf ----------------
__global__ void k_mlp(const float* __restrict__ w1, const float* __restrict__ b1,
                      const float* __restrict__ w2, const float* __restrict__ b2) {
    int l = blockIdx.x;
    int b = blockIdx.y;
    int c = threadIdx.x;
    bool isT = (l < T_);
    int L  = isT ? T_ : F_;
    int ll = isT ? l : l - T_;
    const float* src = isT ? g_meanF : g_meanT;
    float* dst       = isT ? g_zt    : g_zf;

    __shared__ float zs[64];
    __shared__ float hs[8];
    zs[c] = src[((size_t)b*64 + c) * L + ll];
    __syncthreads();
    if (c < 5) {
        float a = b1[c];
        #pragma unroll 8
        for (int i = 0; i < 64; i++) a += w1[c*64 + i] * zs[i];
        hs[c] = fmaxf(a, 0.f);
    }
    __syncthreads();
    float v = b2[c];
    #pragma unroll
    for (int j = 0; j < 5; j++) v += w2[c*5 + j] * hs[j];
    dst[((size_t)b*64 + c) * L + ll] = 1.f / (1.f + expf(-v));
}

// ---------------- K3: att_map ----------------
__global__ void k_attmap(const float* __restrict__ wc, const float* __restrict__ bc) {
    int b = blockIdx.y;
    int f0 = blockIdx.x * 8;
    int tid = threadIdx.x;
    int t0 = tid * 2;
    __shared__ float wcz[8][64];
    for (int i = tid; i < 512; i += 256) {
        int fi = i >> 6, c = i & 63;
        wcz[fi][c] = wc[c] * g_zf[((size_t)b*64 + c) * F_ + f0 + fi];
    }
    __syncthreads();
    float bcv = bc[0];
    float2 acc[8];
    #pragma unroll
    for (int fi = 0; fi < 8; fi++) acc[fi] = make_float2(bcv, bcv);
    const float* ztb = g_zt + (size_t)b * 64 * T_;
    for (int c = 0; c < 64; c++) {
        float2 z2 = *(const float2*)(ztb + (size_t)c * T_ + t0);
        #pragma unroll
        for (int fi = 0; fi < 8; fi++) {
            acc[fi].x += wcz[fi][c] * z2.x;
            acc[fi].y += wcz[fi][c] * z2.y;
        }
    }
    #pragma unroll
    for (int fi = 0; fi < 8; fi++)
        *(float2*)&g_att[((size_t)b*F_ + f0 + fi) * T_ + t0] = acc[fi];
}

// ---------------- K4: HMMA augmented GEMM + BN partial stats ----------------
// Tile: M=128 (t) x N=64 (c), K=128. bf16 truncation hi/lo split, 3 mma passes.
#define AH_OFF 0u
#define AL_OFF 34816u
#define WH_OFF 69632u
#define WL_OFF 87040u
#define PW_OFF 104448u
#define THR_OFF 110592u
#define BOS_OFF 110720u
#define K4_SMEM 110976

__global__ void __launch_bounds__(256, 2) k_main(const float* __restrict__ x,
                                                 const float* __restrict__ bo) {
    extern __shared__ char sm[];
    const uint32_t s0 = smem_u32(sm);
    const int tid = threadIdx.x;
    const int lane = tid & 31;
    const int wid = tid >> 5;
    const int tt = blockIdx.x, f = blockIdx.y, b = blockIdx.z;
    const int t0 = tt * 128;

    // ---- stage W hi/lo, pw, thr, bos ----
    {
        const uint4* wh = (const uint4*)g_Wbh;
        const uint4* wl = (const uint4*)g_Wbl;
        uint4* dh = (uint4*)(sm + WH_OFF);
        uint4* dl = (uint4*)(sm + WL_OFF);
        for (int i = tid; i < 1088; i += 256) { dh[i] = wh[i]; dl[i] = wl[i]; }
        float* pwd = (float*)(sm + PW_OFF);
        for (int i = tid; i < 1536; i += 256) pwd[i] = g_pw[i];
        if (tid < 32) ((float*)(sm + THR_OFF))[tid] = g_thr[tid];
        if (tid < 64) ((float*)(sm + BOS_OFF))[tid] = bo[tid];
    }
    __syncthreads();

    // ---- build augmented A tile (bf16 hi/lo via truncation split, no F2FP) ----
    {
        const int t   = tid & 127;
        const int ch  = (tid >> 7) * 32;
        float a = g_att[((size_t)b*F_ + f) * T_ + t0 + t];
        const float* thrS = (const float*)(sm + THR_OFF);
        int Kc = 0;
        #pragma unroll
        for (int i = 0; i < NTHR_; i++) Kc += (a > thrS[i]) ? 1 : 0;
        const float* pwS = (const float*)(sm + PW_OFF) + Kc;

        const float* xp = x + ((size_t)b*64*256 + f) * 512 + t0 + t;
        char* rowH = sm + AH_OFF + (unsigned)t * 272u;
        char* rowL = sm + AL_OFF + (unsigned)t * 272u;
        #pragma unroll
        for (int c4 = 0; c4 < 32; c4 += 4) {
            int c = ch + c4;
            float v[4], av[4];
            #pragma unroll
            for (int j = 0; j < 4; j++) v[j] = __ldg(xp + (size_t)(c + j) * FT_);
            #pragma unroll
            for (int j = 0; j < 4; j++) av[j] = (a * pwS[(c + j) * 24]) * v[j];
            unsigned hu[4], lu[4], au[4], alu2[4];
            #pragma unroll
            for (int j = 0; j < 4; j++) {
                unsigned u = __float_as_uint(v[j]);
                hu[j] = u & 0xFFFF0000u;
                lu[j] = __float_as_uint(v[j] - __uint_as_float(hu[j]));
                unsigned ua = __float_as_uint(av[j]);
                au[j] = ua & 0xFFFF0000u;
                alu2[j] = __float_as_uint(av[j] - __uint_as_float(au[j]));
            }
            uint2 ph  = make_uint2(__byte_perm(hu[0],  hu[1],  0x7632), __byte_perm(hu[2],  hu[3],  0x7632));
            uint2 pl  = make_uint2(__byte_perm(lu[0],  lu[1],  0x7632), __byte_perm(lu[2],  lu[3],  0x7632));
            uint2 pah = make_uint2(__byte_perm(au[0],  au[1],  0x7632), __byte_perm(au[2],  au[3],  0x7632));
            uint2 pal = make_uint2(__byte_perm(alu2[0],alu2[1],0x7632), __byte_perm(alu2[2],alu2[3],0x7632));
            *(uint2*)(rowH + c*2)        = ph;
            *(uint2*)(rowL + c*2)        = pl;
            *(uint2*)(rowH + 128 + c*2)  = pah;   // cols 64..127 = augmented
            *(uint2*)(rowL + 128 + c*2)  = pal;
        }
    }
    __syncthreads();

    // ---- warp-level HMMA: warp tile 32 (t) x 32 (c) ----
    const int wm = wid & 3;
    const int wn = wid >> 2;
    const int quad = lane >> 3, r8 = lane & 7;

    const int arow = (quad & 1) ? 8 : 0;
    const int akof = (quad & 2) ? 16 : 0;
    uint32_t aH0 = s0 + AH_OFF + (unsigned)(wm*32 + arow + r8) * 272u + akof;
    uint32_t aH1 = aH0 + 16u * 272u;
    const int brow = (quad & 2) ? 8 : 0;
    const int bkof = (quad & 1) ? 16 : 0;
    uint32_t bH0 = s0 + WH_OFF + (unsigned)(wn*32 + brow + r8) * 272u + bkof;
    uint32_t bH1 = bH0 + 16u * 272u;

    float acc[2][4][4];
    #pragma unroll
    for (int ms = 0; ms < 2; ms++)
        #pragma unroll
        for (int nb = 0; nb < 4; nb++)
            #pragma unroll
            for (int e = 0; e < 4; e++) acc[ms][nb][e] = 0.f;

    #pragma unroll 2
    for (int ks = 0; ks < 8; ks++) {
        const uint32_t ko = (unsigned)ks * 32u;
        uint32_t ah[2][4], al[2][4], bh[2][4], bl[2][4];
        ldsm_x4(ah[0], aH0 + ko);
        ldsm_x4(ah[1], aH1 + ko);
        ldsm_x4(al[0], aH0 + AL_OFF - AH_OFF + ko);
        ldsm_x4(al[1], aH1 + AL_OFF - AH_OFF + ko);
        ldsm_x4(bh[0], bH0 + ko);
        ldsm_x4(bh[1], bH1 + ko);
        ldsm_x4(bl[0], bH0 + (WL_OFF - WH_OFF) + ko);
        ldsm_x4(bl[1], bH1 + (WL_OFF - WH_OFF) + ko);
        #pragma unroll
        for (int ms = 0; ms < 2; ms++) {
            #pragma unroll
            for (int nb = 0; nb < 4; nb++) {
                const uint32_t* bhp = &bh[nb >> 1][(nb & 1) * 2];
                const uint32_t* blp = &bl[nb >> 1][(nb & 1) * 2];
                mma16816(acc[ms][nb], ah[ms], bhp);
                mma16816(acc[ms][nb], ah[ms], blp);
                mma16816(acc[ms][nb], al[ms], bhp);
            }
        }
    }
    __syncthreads();

    // ---- smem transpose stat[c][t], stride 132 ----
    float* stat = (float*)sm;
    {
        const int r = lane >> 2, nq = lane & 3;
        #pragma unroll
        for (int ms = 0; ms < 2; ms++) {
            #pragma unroll
            for (int nb = 0; nb < 4; nb++) {
                int tl = wm*32 + ms*16 + r;
                int cc = wn*32 + nb*8 + 2*nq;
                stat[(cc  )*132 + tl    ] = acc[ms][nb][0];
                stat[(cc+1)*132 + tl    ] = acc[ms][nb][1];
                stat[(cc  )*132 + tl + 8] = acc[ms][nb][2];
                stat[(cc+1)*132 + tl + 8] = acc[ms][nb][3];
            }
        }
    }
    __syncthreads();

    // ---- coalesced g_o writes + BN partials ----
    float* ssum = (float*)(sm + WH_OFF);
    float* ssq  = (float*)(sm + WH_OFF + 1024);
    {
        const int c = tid >> 2, q = tid & 3;
        const float bos = ((const float*)(sm + BOS_OFF))[c];
        const float* row = stat + c*132 + q*32;
        float* ob = g_o + ((size_t)b*64*256 + (size_t)c*256 + f) * 512 + t0 + q*32;
        float s = 0.f, sq = 0.f;
        #pragma unroll
        for (int i = 0; i < 8; i++) {
            float4 v = *(const float4*)(row + i*4);
            v.x += bos; v.y += bos; v.z += bos; v.w += bos;
            s  += (v.x + v.y) + (v.z + v.w);
            sq += (v.x*v.x + v.y*v.y) + (v.z*v.z + v.w*v.w);
            *(float4*)(ob + i*4) = v;
        }
        ssum[c*4 + q] = s;
        ssq [c*4 + q] = sq;
    }
    __syncthreads();
    if (tid < 64) {
        int cta = ((b*256 + f) << 2) + tt;
        float s  = ssum[tid*4] + ssum[tid*4+1] + ssum[tid*4+2] + ssum[tid*4+3];
        float sq = ssq [tid*4] + ssq [tid*4+1] + ssq [tid*4+2] + ssq [tid*4+3];
        g_part[(size_t)cta*128 + tid]      = s;
        g_part[(size_t)cta*128 + 64 + tid] = sq;
    }
}

// ---------------- K5a: parallel partial reduce (128 CTAs, 64 rows each) ----------------
__global__ void k_stats1() {
    int j = threadIdx.x;           // 0..127
    int r0 = blockIdx.x * 64;
    float s = 0.f;
    #pragma unroll 8
    for (int r = 0; r < 64; r++) s += g_part[(size_t)(r0 + r)*128 + j];
    g_part2[blockIdx.x*128 + j] = s;
}

// ---------------- K5b: final stats (1 CTA, double) ----------------
__global__ void k_stats2(const float* __restrict__ gamma, const float* __restrict__ beta) {
    __shared__ double acc[128];
    int j = threadIdx.x;           // 0..127
    double s = 0.0;
    for (int i = 0; i < 128; i++) s += (double)g_part2[i*128 + j];
    acc[j] = s;
    __syncthreads();
    if (j < 64) {
        double mu  = acc[j] / NPOSF;
        double var = acc[64 + j] / NPOSF - mu * mu;
        float sc = gamma[j] * (float)(1.0 / sqrt(var + 1e-5));
        g_scale[j] = sc;
        g_shift[j] = beta[j] - (float)mu * sc;
    }
}

// ---------------- K6: normalize + ReLU streaming ----------------
__global__ void k_norm(float* __restrict__ out) {
    __shared__ float sc[64], sh[64];
    if (threadIdx.x < 64) { sc[threadIdx.x] = g_scale[threadIdx.x]; sh[threadIdx.x] = g_shift[threadIdx.x]; }
    __syncthreads();
    const size_t n4 = (size_t)B_ * C_ * FT_ / 4;
    const float4* src = (const float4*)g_o;
    float4* dst = (float4*)out;
    for (size_t i = (size_t)blockIdx.x * blockDim.x + threadIdx.x; i < n4;
         i += (size_t)gridDim.x * blockDim.x) {
        float4 v = src[i];
        int c = (int)(i >> 15) & 63;
        float s = sc[c], t = sh[c];
        v.x = fmaxf(fmaf(v.x, s, t), 0.f);
        v.y = fmaxf(fmaf(v.y, s, t), 0.f);
        v.z = fmaxf(fmaf(v.z, s, t), 0.f);
        v.w = fmaxf(fmaf(v.w, s, t), 0.f);
        dst[i] = v;
    }
}

// ---------------- launch ----------------
extern "C" void kernel_launch(void* const* d_in, const int* in_sizes, int n_in,
                              void* d_out, int out_size) {
    const float* x     = (const float*)d_in[0];
    const float* w1    = (const float*)d_in[1];
    const float* b1    = (const float*)d_in[2];
    const float* w2    = (const float*)d_in[3];
    const float* b2    = (const float*)d_in[4];
    const float* wc    = (const float*)d_in[5];
    const float* bc    = (const float*)d_in[6];
    const float* wc2   = (const float*)d_in[7];
    const float* bc2   = (const float*)d_in[8];
    const float* wo    = (const float*)d_in[9];
    const float* bo    = (const float*)d_in[10];
    const float* gamma = (const float*)d_in[11];
    const float* beta  = (const float*)d_in[12];
    float* out = (float*)d_out;

    cudaFuncSetAttribute(k_main, cudaFuncAttributeMaxDynamicSharedMemorySize, K4_SMEM);

    k_reduce_prep<<<513, 256>>>(x, wc2, bc2, wo);
    k_mlp<<<dim3(768, B_), 64>>>(w1, b1, w2, b2);
    k_attmap<<<dim3(F_/8, B_), 256>>>(wc, bc);
    k_main<<<dim3(4, F_, B_), 256, K4_SMEM>>>(x, bo);
    k_stats1<<<128, 128>>>();
    k_stats2<<<1, 128>>>(gamma, beta);
    k_norm<<<4096, 256>>>(out);
}

// round 6
// speedup vs baseline: 3.0789x; 1.6652x over previous
#include <cuda_runtime.h>
#include <cuda_bf16.h>
#include <cstdint>

#define B_ 8
#define C_ 64
#define F_ 256
#define T_ 512
#define FT_ (F_*T_)                 /* 131072 */
#define NTHR_ 23
#define NPOSF 1048576.0

// ---------------- device scratch (static; no runtime allocation) ----------------
__device__ float  g_meanF[B_*C_*T_];
__device__ float  g_meanT[B_*C_*F_];
__device__ float  g_zt[B_*C_*T_];
__device__ float  g_zf[B_*C_*F_];
__device__ float  g_att[B_*F_*T_];
__device__ float  g_o[(size_t)B_*C_*F_*T_];   // 256 MB pre-BN activations
__device__ float  g_part[8192*128];
__device__ float  g_part2[128*128];
__device__ float  g_thr[32];
__device__ float  g_pw[64*24];                // prefix sums of wc2
__device__ __align__(16) unsigned short g_Wbh[64*136];  // W bf16 hi, padded row-major [c][k]
__device__ __align__(16) unsigned short g_Wbl[64*136];  // W bf16 lo
__device__ float  g_scale[64];
__device__ float  g_shift[64];

__device__ __forceinline__ uint32_t smem_u32(const void* p) {
    uint32_t a;
    asm("{ .reg .u64 t; cvta.to.shared.u64 t, %1; cvt.u32.u64 %0, t; }" : "=r"(a) : "l"(p));
    return a;
}
__device__ __forceinline__ void ldsm_x4(uint32_t* r, uint32_t addr) {
    asm volatile("ldmatrix.sync.aligned.m8n8.x4.shared.b16 {%0,%1,%2,%3}, [%4];"
        : "=r"(r[0]), "=r"(r[1]), "=r"(r[2]), "=r"(r[3]) : "r"(addr));
}
__device__ __forceinline__ void mma16816(float* d, const uint32_t* a, const uint32_t* b) {
    asm volatile("mma.sync.aligned.m16n8k16.row.col.f32.bf16.bf16.f32 "
        "{%0,%1,%2,%3}, {%4,%5,%6,%7}, {%8,%9}, {%0,%1,%2,%3};"
        : "+f"(d[0]), "+f"(d[1]), "+f"(d[2]), "+f"(d[3])
        : "r"(a[0]), "r"(a[1]), "r"(a[2]), "r"(a[3]), "r"(b[0]), "r"(b[1]));
}

// ---------------- K1: means over F/T per plane; block 512 = table prep ----------------
__global__ void k_reduce_prep(const float* __restrict__ x,
                              const float* __restrict__ wc2, const float* __restrict__ bc2,
                              const float* __restrict__ wo) {
    if (blockIdx.x == 512) {
        int tid = threadIdx.x;  // 256
        if (tid == 0) {
            double cnt = 0.0;
            for (int i = 1; i <= NTHR_; i++) { cnt += (double)i / 300.0; g_thr[i-1] = (float)cnt; }
        }
        if (tid < 64) {
            int c = tid;
            float s = 0.f;
            g_pw[c*24 + 0] = 0.f;
            for (int j = 1; j <= NTHR_; j++) { s += wc2[c*NTHR_ + (j-1)]; g_pw[c*24 + j] = s; }
        }
        if (tid < 128) {
            int k = tid;  // augmented weight W[c][k]
            for (int c = 0; c < 64; c++) {
                float w;
                if (k < 64) w = wo[c*128 + k] + wo[c*128 + 64 + k] * bc2[k];
                else        w = wo[c*128 + k];
                __nv_bfloat16 hi = __float2bfloat16_rn(w);
                __nv_bfloat16 lo = __float2bfloat16_rn(w - __bfloat162float(hi));
                g_Wbh[c*136 + k] = __bfloat16_as_ushort(hi);
                g_Wbl[c*136 + k] = __bfloat16_as_ushort(lo);
            }
        }
        return;
    }
    int bc = blockIdx.x;
    const float* plane = x + (size_t)bc * FT_;
    int w = threadIdx.x >> 5, lane = threadIdx.x & 31;
    __shared__ float colp[8][512];

    float4 cacc[4];
    #pragma unroll
    for (int it = 0; it < 4; it++) cacc[it] = make_float4(0.f, 0.f, 0.f, 0.f);

    for (int f = w; f < F_; f += 8) {
        const float4* row = (const float4*)(plane + (size_t)f * T_);
        float rsum = 0.f;
        #pragma unroll
        for (int it = 0; it < 4; it++) {
            float4 v = row[lane + 32*it];
            rsum += (v.x + v.y) + (v.z + v.w);
            cacc[it].x += v.x; cacc[it].y += v.y; cacc[it].z += v.z; cacc[it].w += v.w;
        }
        #pragma unroll
        for (int off = 16; off > 0; off >>= 1) rsum += __shfl_xor_sync(0xffffffffu, rsum, off);
        if (lane == 0) g_meanT[(size_t)bc * F_ + f] = rsum * (1.f / (float)T_);
    }
    #pragma unroll
    for (int it = 0; it < 4; it++) ((float4*)colp[w])[lane + 32*it] = cacc[it];
    __syncthreads();
    for (int t = threadIdx.x; t < T_; t += 256) {
        float s = 0.f;
        #pragma unroll
        for (int ww = 0; ww < 8; ww++) s += colp[ww][t];
        g_meanF[(size_t)bc * T_ + t] = s * (1.f / (float)F_);
    }
}

// ---------------- K2: channel MLP -> zt, zf ----------------
__global__ void k_mlp(const float* __restrict__ w1, const float* __restrict__ b1,
                      const float* __restrict__ w2, const float* __restrict__ b2) {
    int l = blockIdx.x;
    int b = blockIdx.y;
    int c = threadIdx.x;
    bool isT = (l < T_);
    int L  = isT ? T_ : F_;
    int ll = isT ? l : l - T_;
    const float* src = isT ? g_meanF : g_meanT;
    float* dst       = isT ? g_zt    : g_zf;

    __shared__ float zs[64];
    __shared__ float hs[8];
    zs[c] = src[((size_t)b*64 + c) * L + ll];
    __syncthreads();
    if (c < 5) {
        float a = b1[c];
        #pragma unroll 8
        for (int i = 0; i < 64; i++) a += w1[c*64 + i] * zs[i];
        hs[c] = fmaxf(a, 0.f);
    }
    __syncthreads();
    float v = b2[c];
    #pragma unroll
    for (int j = 0; j < 5; j++) v += w2[c*5 + j] * hs[j];
    dst[((size_t)b*64 + c) * L + ll] = 1.f / (1.f + expf(-v));
}

// ---------------- K3: att_map ----------------
__global__ void k_attmap(const float* __restrict__ wc, const float* __restrict__ bc) {
    int b = blockIdx.y;
    int f0 = blockIdx.x * 8;
    int tid = threadIdx.x;
    int t0 = tid * 2;
    __shared__ float wcz[8][64];
    for (int i = tid; i < 512; i += 256) {
        int fi = i >> 6, c = i & 63;
        wcz[fi][c] = wc[c] * g_zf[((size_t)b*64 + c) * F_ + f0 + fi];
    }
    __syncthreads();
    float bcv = bc[0];
    float2 acc[8];
    #pragma unroll
    for (int fi = 0; fi < 8; fi++) acc[fi] = make_float2(bcv, bcv);
    const float* ztb = g_zt + (size_t)b * 64 * T_;
    for (int c = 0; c < 64; c++) {
        float2 z2 = *(const float2*)(ztb + (size_t)c * T_ + t0);
        #pragma unroll
        for (int fi = 0; fi < 8; fi++) {
            acc[fi].x += wcz[fi][c] * z2.x;
            acc[fi].y += wcz[fi][c] * z2.y;
        }
    }
    #pragma unroll
    for (int fi = 0; fi < 8; fi++)
        *(float2*)&g_att[((size_t)b*F_ + f0 + fi) * T_ + t0] = acc[fi];
}

// ---------------- K4: HMMA augmented GEMM, 4 tiles per CTA, x prefetched ----------------
#define AH_OFF 0u
#define AL_OFF 34816u
#define WH_OFF 69632u
#define WL_OFF 87040u
#define PW_OFF 104448u
#define THR_OFF 110592u
#define BOS_OFF 110720u
#define K4_SMEM 110976

__global__ void __launch_bounds__(256, 2) k_main(const float* __restrict__ x,
                                                 const float* __restrict__ bo) {
    extern __shared__ char sm[];
    const uint32_t s0 = smem_u32(sm);
    const int tid = threadIdx.x;
    const int lane = tid & 31;
    const int wid = tid >> 5;
    const int f = blockIdx.x, b = blockIdx.y;

    // ---- stage W hi/lo, pw, thr, bos (once per CTA / 4 tiles) ----
    {
        const uint4* wh = (const uint4*)g_Wbh;
        const uint4* wl = (const uint4*)g_Wbl;
        uint4* dh = (uint4*)(sm + WH_OFF);
        uint4* dl = (uint4*)(sm + WL_OFF);
        for (int i = tid; i < 1088; i += 256) { dh[i] = wh[i]; dl[i] = wl[i]; }
        float* pwd = (float*)(sm + PW_OFF);
        for (int i = tid; i < 1536; i += 256) pwd[i] = g_pw[i];
        if (tid < 32) ((float*)(sm + THR_OFF))[tid] = g_thr[tid];
        if (tid < 64) ((float*)(sm + BOS_OFF))[tid] = bo[tid];
    }

    const int t  = tid & 127;
    const int ch = (tid >> 7) * 32;
    const float* xbase = x + ((size_t)b*64*256 + f) * 512 + t;   // + ch*FT_ + t0
    // prefetch att for all 4 tiles + x for tile 0
    float a4[4];
    #pragma unroll
    for (int i = 0; i < 4; i++) a4[i] = g_att[((size_t)b*F_ + f) * T_ + i*128 + t];
    float xv[32];
    #pragma unroll
    for (int j = 0; j < 32; j++) xv[j] = __ldg(xbase + (size_t)(ch + j) * FT_);

    __syncthreads();

    // warp HMMA geometry (fixed across tiles)
    const int wm = wid & 3;
    const int wn = wid >> 2;
    const int quad = lane >> 3, r8 = lane & 7;
    const int arow = (quad & 1) ? 8 : 0;
    const int akof = (quad & 2) ? 16 : 0;
    const uint32_t aH0 = s0 + AH_OFF + (unsigned)(wm*32 + arow + r8) * 272u + akof;
    const uint32_t aH1 = aH0 + 16u * 272u;
    const int brow = (quad & 2) ? 8 : 0;
    const int bkof = (quad & 1) ? 16 : 0;
    const uint32_t bH0 = s0 + WH_OFF + (unsigned)(wn*32 + brow + r8) * 272u + bkof;
    const uint32_t bH1 = bH0 + 16u * 272u;

    for (int tt = 0; tt < 4; tt++) {
        const int t0 = tt * 128;
        // ---- build A tile from prefetched xv (truncation hi/lo split, no cvt) ----
        {
            float a = a4[tt];
            const float* thrS = (const float*)(sm + THR_OFF);
            int Kc = 0;
            #pragma unroll
            for (int i = 0; i < NTHR_; i++) Kc += (a > thrS[i]) ? 1 : 0;
            const float* pwS = (const float*)(sm + PW_OFF) + Kc;

            char* rowH = sm + AH_OFF + (unsigned)t * 272u;
            char* rowL = sm + AL_OFF + (unsigned)t * 272u;
            #pragma unroll
            for (int c4 = 0; c4 < 32; c4 += 4) {
                int c = ch + c4;
                float v[4], av[4];
                #pragma unroll
                for (int j = 0; j < 4; j++) v[j] = xv[c4 + j];
                #pragma unroll
                for (int j = 0; j < 4; j++) av[j] = (a * pwS[(c + j) * 24]) * v[j];
                unsigned hu[4], lu[4], au[4], alu2[4];
                #pragma unroll
                for (int j = 0; j < 4; j++) {
                    unsigned u = __float_as_uint(v[j]);
                    hu[j] = u & 0xFFFF0000u;
                    lu[j] = __float_as_uint(v[j] - __uint_as_float(hu[j]));
                    unsigned ua = __float_as_uint(av[j]);
                    au[j] = ua & 0xFFFF0000u;
                    alu2[j] = __float_as_uint(av[j] - __uint_as_float(au[j]));
                }
                uint2 ph  = make_uint2(__byte_perm(hu[0],  hu[1],  0x7632), __byte_perm(hu[2],  hu[3],  0x7632));
                uint2 pl  = make_uint2(__byte_perm(lu[0],  lu[1],  0x7632), __byte_perm(lu[2],  lu[3],  0x7632));
                uint2 pah = make_uint2(__byte_perm(au[0],  au[1],  0x7632), __byte_perm(au[2],  au[3],  0x7632));
                uint2 pal = make_uint2(__byte_perm(alu2[0],alu2[1],0x7632), __byte_perm(alu2[2],alu2[3],0x7632));
                *(uint2*)(rowH + c*2)        = ph;
                *(uint2*)(rowL + c*2)        = pl;
                *(uint2*)(rowH + 128 + c*2)  = pah;
                *(uint2*)(rowL + 128 + c*2)  = pal;
            }
        }
        // ---- prefetch x for next tile (latency hidden behind mma + epilogue) ----
        if (tt < 3) {
            const float* xn = xbase + (tt + 1) * 128;
            #pragma unroll
            for (int j = 0; j < 32; j++) xv[j] = __ldg(xn + (size_t)(ch + j) * FT_);
        }
        __syncthreads();

        // ---- HMMA: warp tile 32(t) x 32(c), 3-pass bf16 split ----
        float acc[2][4][4];
        #pragma unroll
        for (int ms = 0; ms < 2; ms++)
            #pragma unroll
            for (int nb = 0; nb < 4; nb++)
                #pragma unroll
                for (int e = 0; e < 4; e++) acc[ms][nb][e] = 0.f;

        #pragma unroll 2
        for (int ks = 0; ks < 8; ks++) {
            const uint32_t ko = (unsigned)ks * 32u;
            uint32_t ah[2][4], al[2][4], bh[2][4], bl[2][4];
            ldsm_x4(ah[0], aH0 + ko);
            ldsm_x4(ah[1], aH1 + ko);
            ldsm_x4(al[0], aH0 + (AL_OFF - AH_OFF) + ko);
            ldsm_x4(al[1], aH1 + (AL_OFF - AH_OFF) + ko);
            ldsm_x4(bh[0], bH0 + ko);
            ldsm_x4(bh[1], bH1 + ko);
            ldsm_x4(bl[0], bH0 + (WL_OFF - WH_OFF) + ko);
            ldsm_x4(bl[1], bH1 + (WL_OFF - WH_OFF) + ko);
            #pragma unroll
            for (int ms = 0; ms < 2; ms++) {
                #pragma unroll
                for (int nb = 0; nb < 4; nb++) {
                    const uint32_t* bhp = &bh[nb >> 1][(nb & 1) * 2];
                    const uint32_t* blp = &bl[nb >> 1][(nb & 1) * 2];
                    mma16816(acc[ms][nb], ah[ms], bhp);
                    mma16816(acc[ms][nb], ah[ms], blp);
                    mma16816(acc[ms][nb], al[ms], bhp);
                }
            }
        }
        __syncthreads();   // all warps done reading A before transpose overwrites

        // ---- smem transpose stat[c][t], stride 132 (in A-hi region) ----
        float* stat = (float*)sm;
        {
            const int r = lane >> 2, nq = lane & 3;
            #pragma unroll
            for (int ms = 0; ms < 2; ms++) {
                #pragma unroll
                for (int nb = 0; nb < 4; nb++) {
                    int tl = wm*32 + ms*16 + r;
                    int cc = wn*32 + nb*8 + 2*nq;
                    stat[(cc  )*132 + tl    ] = acc[ms][nb][0];
                    stat[(cc+1)*132 + tl    ] = acc[ms][nb][1];
                    stat[(cc  )*132 + tl + 8] = acc[ms][nb][2];
                    stat[(cc+1)*132 + tl + 8] = acc[ms][nb][3];
                }
            }
        }
        __syncthreads();

        // ---- coalesced g_o writes + BN partials (scratch in A-lo region) ----
        float* ssum = (float*)(sm + AL_OFF);
        float* ssq  = (float*)(sm + AL_OFF + 1024);
        {
            const int c = tid >> 2, q = tid & 3;
            const float bos = ((const float*)(sm + BOS_OFF))[c];
            const float* row = stat + c*132 + q*32;
            float* ob = g_o + ((size_t)b*64*256 + (size_t)c*256 + f) * 512 + t0 + q*32;
            float s = 0.f, sq = 0.f;
            #pragma unroll
            for (int i = 0; i < 8; i++) {
                float4 v = *(const float4*)(row + i*4);
                v.x += bos; v.y += bos; v.z += bos; v.w += bos;
                s  += (v.x + v.y) + (v.z + v.w);
                sq += (v.x*v.x + v.y*v.y) + (v.z*v.z + v.w*v.w);
                *(float4*)(ob + i*4) = v;
            }
            ssum[c*4 + q] = s;
            ssq [c*4 + q] = sq;
        }
        __syncthreads();
        if (tid < 64) {
            int cta = ((b*256 + f) << 2) + tt;
            float s  = ssum[tid*4] + ssum[tid*4+1] + ssum[tid*4+2] + ssum[tid*4+3];
            float sq = ssq [tid*4] + ssq [tid*4+1] + ssq [tid*4+2] + ssq [tid*4+3];
            g_part[(size_t)cta*128 + tid]      = s;
            g_part[(size_t)cta*128 + 64 + tid] = sq;
        }
        __syncthreads();   // epilogue reads done before next build overwrites A
    }
}

// ---------------- K5a: parallel partial reduce (128 CTAs, 64 rows each) ----------------
__global__ void k_stats1() {
    int j = threadIdx.x;           // 0..127
    int r0 = blockIdx.x * 64;
    float s = 0.f;
    #pragma unroll 8
    for (int r = 0; r < 64; r++) s += g_part[(size_t)(r0 + r)*128 + j];
    g_part2[blockIdx.x*128 + j] = s;
}

// ---------------- K5b: final stats (1 CTA, double) ----------------
__global__ void k_stats2(const float* __restrict__ gamma, const float* __restrict__ beta) {
    __shared__ double acc[128];
    int j = threadIdx.x;           // 0..127
    double s = 0.0;
    for (int i = 0; i < 128; i++) s += (double)g_part2[i*128 + j];
    acc[j] = s;
    __syncthreads();
    if (j < 64) {
        double mu  = acc[j] / NPOSF;
        double var = acc[64 + j] / NPOSF - mu * mu;
        float sc = gamma[j] * (float)(1.0 / sqrt(var + 1e-5));
        g_scale[j] = sc;
        g_shift[j] = beta[j] - (float)mu * sc;
    }
}

// ---------------- K6: normalize + ReLU streaming ----------------
__global__ void k_norm(float* __restrict__ out) {
    __shared__ float sc[64], sh[64];
    if (threadIdx.x < 64) { sc[threadIdx.x] = g_scale[threadIdx.x]; sh[threadIdx.x] = g_shift[threadIdx.x]; }
    __syncthreads();
    const size_t n4 = (size_t)B_ * C_ * FT_ / 4;
    const float4* src = (const float4*)g_o;
    float4* dst = (float4*)out;
    for (size_t i = (size_t)blockIdx.x * blockDim.x + threadIdx.x; i < n4;
         i += (size_t)gridDim.x * blockDim.x) {
        float4 v = src[i];
        int c = (int)(i >> 15) & 63;
        float s = sc[c], t = sh[c];
        v.x = fmaxf(fmaf(v.x, s, t), 0.f);
        v.y = fmaxf(fmaf(v.y, s, t), 0.f);
        v.z = fmaxf(fmaf(v.z, s, t), 0.f);
        v.w = fmaxf(fmaf(v.w, s, t), 0.f);
        dst[i] = v;
    }
}

// ---------------- launch ----------------
extern "C" void kernel_launch(void* const* d_in, const int* in_sizes, int n_in,
                              void* d_out, int out_size) {
    const float* x     = (const float*)d_in[0];
    const float* w1    = (const float*)d_in[1];
    const float* b1    = (const float*)d_in[2];
    const float* w2    = (const float*)d_in[3];
    const float* b2    = (const float*)d_in[4];
    const float* wc    = (const float*)d_in[5];
    const float* bc    = (const float*)d_in[6];
    const float* wc2   = (const float*)d_in[7];
    const float* bc2   = (const float*)d_in[8];
    const float* wo    = (const float*)d_in[9];
    const float* bo    = (const float*)d_in[10];
    const float* gamma = (const float*)d_in[11];
    const float* beta  = (const float*)d_in[12];
    float* out = (float*)d_out;

    cudaFuncSetAttribute(k_main, cudaFuncAttributeMaxDynamicSharedMemorySize, K4_SMEM);

    k_reduce_prep<<<513, 256>>>(x, wc2, bc2, wo);
    k_mlp<<<dim3(768, B_), 64>>>(w1, b1, w2, b2);
    k_attmap<<<dim3(F_/8, B_), 256>>>(wc, bc);
    k_main<<<dim3(F_, B_), 256, K4_SMEM>>>(x, bo);
    k_stats1<<<128, 128>>>();
    k_stats2<<<1, 128>>>(gamma, beta);
    k_norm<<<4096, 256>>>(out);
}